// round 10
// baseline (speedup 1.0000x reference)
#include <cuda_runtime.h>
#include <cuda_bf16.h>
#include <cstdint>

#define NN 8192
#define DD 128
#define TAU 0.1f
#define RSH 136                  // smem row stride in halves (128 data + 8 pad)
#define RSB 272                  // row stride in bytes
#define TILE_B 17408             // one K-or-V tile: 64*136*2 bytes
#define SMEM_TOTAL 69632         // K0,K1,V0,V1
#define SM_K0 0
#define SM_K1 TILE_B
#define SM_V0 (2*TILE_B)
#define SM_V1 (3*TILE_B)
#define SQRT_LOG2E 1.2011224087864498f

// MLP smem layout (bytes, within the same 69632 dynamic allocation)
#define MW_OFF 0                 // W tile: 128 x RSH bf16 = 34816
#define MA_OFF 34816             // A tile: 64 x RSH bf16 = 17408
#define MH_OFF 52224             // H tile: 64 x RSH bf16 = 17408

static __device__ __nv_bfloat16 g_t[NN * DD];   // t' = MLP(Z)*sqrt(log2 e), bf16
static __device__ __nv_bfloat16 g_zb[NN * DD];  // Z in bf16 (V operand)
static __device__ float g_diag[NN];             // per-row diagonal logit (log2 units)

__device__ __forceinline__ uint32_t packbf(float a, float b) {
    __nv_bfloat162 h = __floats2bfloat162_rn(a, b);
    return *reinterpret_cast<uint32_t*>(&h);
}

__device__ __forceinline__ float ex2(float x) {
    float y;
    asm("ex2.approx.ftz.f32 %0, %1;" : "=f"(y) : "f"(x));
    return y;
}

__device__ __forceinline__ uint32_t smem_u32(const void* p) {
    return (uint32_t)__cvta_generic_to_shared(p);
}

__device__ __forceinline__ void mma16816(float c[4], const uint32_t a[4],
                                         uint32_t b0, uint32_t b1) {
    asm volatile(
        "mma.sync.aligned.m16n8k16.row.col.f32.bf16.bf16.f32 "
        "{%0,%1,%2,%3}, {%4,%5,%6,%7}, {%8,%9}, {%0,%1,%2,%3};\n"
        : "+f"(c[0]), "+f"(c[1]), "+f"(c[2]), "+f"(c[3])
        : "r"(a[0]), "r"(a[1]), "r"(a[2]), "r"(a[3]), "r"(b0), "r"(b1));
}

__device__ __forceinline__ void ldm_x4(uint32_t& r0, uint32_t& r1,
                                       uint32_t& r2, uint32_t& r3, uint32_t a) {
    asm volatile("ldmatrix.sync.aligned.m8n8.x4.shared.b16 {%0,%1,%2,%3}, [%4];\n"
                 : "=r"(r0), "=r"(r1), "=r"(r2), "=r"(r3) : "r"(a));
}
__device__ __forceinline__ void ldm_x4_t(uint32_t& r0, uint32_t& r1,
                                         uint32_t& r2, uint32_t& r3, uint32_t a) {
    asm volatile("ldmatrix.sync.aligned.m8n8.x4.trans.shared.b16 {%0,%1,%2,%3}, [%4];\n"
                 : "=r"(r0), "=r"(r1), "=r"(r2), "=r"(r3) : "r"(a));
}

__device__ __forceinline__ void cp_async16(uint32_t s, const void* g) {
    asm volatile("cp.async.cg.shared.global [%0], [%1], 16;\n" :: "r"(s), "l"(g));
}
__device__ __forceinline__ void cp_commit() {
    asm volatile("cp.async.commit_group;\n");
}
template <int N> __device__ __forceinline__ void cp_wait() {
    asm volatile("cp.async.wait_group %0;\n" :: "n"(N));
}

extern __shared__ __align__(16) unsigned char dynsmem[];

// ---------------------------------------------------------------------------
// MLP (tensor-core, unchanged from R8 pass): t' -> g_t, Zb -> g_zb, diag.
// ---------------------------------------------------------------------------
__global__ __launch_bounds__(256) void mlp_kernel(
    const float* __restrict__ Z, const float* __restrict__ W1,
    const float* __restrict__ b1, const float* __restrict__ W2,
    const float* __restrict__ b2)
{
    __nv_bfloat16* sW = (__nv_bfloat16*)(dynsmem + MW_OFF);
    __nv_bfloat16* sA = (__nv_bfloat16*)(dynsmem + MA_OFF);
    __nv_bfloat16* sH = (__nv_bfloat16*)(dynsmem + MH_OFF);
    const uint32_t sWb = smem_u32(sW);
    const uint32_t sAb = smem_u32(sA);
    const uint32_t sHb = smem_u32(sH);

    const int tid = threadIdx.x;
    const int lane = tid & 31;
    const int warp = tid >> 5;
    const int mrow = (warp & 3) * 16;
    const int nh = (warp >> 2) * 64;
    const int g = lane >> 2;
    const int t4 = lane & 3;
    const int rb = blockIdx.x * 64;

    for (int i = tid; i < 64 * 128; i += 256) {
        int r = i >> 7, c = i & 127;
        __nv_bfloat16 z = __float2bfloat16(Z[(rb + r) * 128 + c]);
        sA[r * RSH + c] = z;
        g_zb[rb * 128 + i] = z;
    }
    for (int i = tid; i < 128 * 128; i += 256) {
        int r = i >> 7, c = i & 127;
        sW[r * RSH + c] = __float2bfloat16(W1[i]);
    }
    __syncthreads();

    const int arow = mrow + (lane & 7) + ((lane >> 3) & 1) * 8;
    const int acol = (lane >> 4) * 8;
    const int brow = lane & 15;
    const int bcol = (lane >> 4) * 8;

    uint32_t af[8][4];
#pragma unroll
    for (int kc = 0; kc < 8; kc++)
        ldm_x4(af[kc][0], af[kc][1], af[kc][2], af[kc][3],
               sAb + arow * RSB + (kc * 16 + acol) * 2);

    float acc[8][4];
#pragma unroll
    for (int j = 0; j < 8; j++) {
        acc[j][0] = 0.f; acc[j][1] = 0.f; acc[j][2] = 0.f; acc[j][3] = 0.f;
    }
#pragma unroll
    for (int nc16 = 0; nc16 < 4; nc16++) {
#pragma unroll
        for (int kc = 0; kc < 8; kc++) {
            uint32_t r0, r1, r2, r3;
            ldm_x4_t(r0, r1, r2, r3,
                     sWb + (kc * 16 + brow) * RSB + (nh + nc16 * 16 + bcol) * 2);
            mma16816(acc[2 * nc16], af[kc], r0, r1);
            mma16816(acc[2 * nc16 + 1], af[kc], r2, r3);
        }
    }
#pragma unroll
    for (int j = 0; j < 8; j++) {
        int ncol = nh + (j >> 1) * 16 + (j & 1) * 8 + 2 * t4;
        float bb0 = b1[ncol], bb1 = b1[ncol + 1];
        float h0 = fmaxf(acc[j][0] + bb0, 0.f);
        float h1 = fmaxf(acc[j][1] + bb1, 0.f);
        float h2 = fmaxf(acc[j][2] + bb0, 0.f);
        float h3 = fmaxf(acc[j][3] + bb1, 0.f);
        *(uint32_t*)&sH[(mrow + g) * RSH + ncol] = packbf(h0, h1);
        *(uint32_t*)&sH[(mrow + g + 8) * RSH + ncol] = packbf(h2, h3);
    }
    __syncthreads();

    for (int i = tid; i < 128 * 128; i += 256) {
        int r = i >> 7, c = i & 127;
        sW[r * RSH + c] = __float2bfloat16(W2[i]);
    }
#pragma unroll
    for (int kc = 0; kc < 8; kc++)
        ldm_x4(af[kc][0], af[kc][1], af[kc][2], af[kc][3],
               sHb + arow * RSB + (kc * 16 + acol) * 2);
#pragma unroll
    for (int j = 0; j < 8; j++) {
        acc[j][0] = 0.f; acc[j][1] = 0.f; acc[j][2] = 0.f; acc[j][3] = 0.f;
    }
    __syncthreads();

#pragma unroll
    for (int nc16 = 0; nc16 < 4; nc16++) {
#pragma unroll
        for (int kc = 0; kc < 8; kc++) {
            uint32_t r0, r1, r2, r3;
            ldm_x4_t(r0, r1, r2, r3,
                     sWb + (kc * 16 + brow) * RSB + (nh + nc16 * 16 + bcol) * 2);
            mma16816(acc[2 * nc16], af[kc], r0, r1);
            mma16816(acc[2 * nc16 + 1], af[kc], r2, r3);
        }
    }
#pragma unroll
    for (int j = 0; j < 8; j++) {
        int ncol = nh + (j >> 1) * 16 + (j & 1) * 8 + 2 * t4;
        float bb0 = b2[ncol], bb1 = b2[ncol + 1];
        uint32_t p0 = packbf((acc[j][0] + bb0) * SQRT_LOG2E,
                             (acc[j][1] + bb1) * SQRT_LOG2E);
        uint32_t p1 = packbf((acc[j][2] + bb0) * SQRT_LOG2E,
                             (acc[j][3] + bb1) * SQRT_LOG2E);
        int r0r = mrow + g, r1r = mrow + g + 8;
        *(uint32_t*)&sA[r0r * RSH + ncol] = p0;
        *(uint32_t*)&sA[r1r * RSH + ncol] = p1;
        *(uint32_t*)&g_t[(rb + r0r) * 128 + ncol] = p0;
        *(uint32_t*)&g_t[(rb + r1r) * 128 + ncol] = p1;
    }
    __syncthreads();

    if (tid < 64) {
        float s = 0.f;
#pragma unroll
        for (int k = 0; k < 128; k++) {
            float v = __bfloat162float(sA[tid * RSH + k]);
            s += v * v;
        }
        g_diag[rb + tid] = s;
    }
}

// ---------------------------------------------------------------------------
// Flash kernel v4: cross-tile pipelined. Per iter: S(kt) mma -> PV(kt-1) mma
// (independent of S results) -> prefetch -> softmax(kt) producing pf for next
// iter. Softmax's scoreboard wait on S is covered by PV issue; MUFU overlaps
// PV drain. K prefetch distance 2, V distance 1; 4 disjoint buffers.
// ---------------------------------------------------------------------------
__device__ __forceinline__ void load_K_async(uint32_t sbase, int buf, int kt,
                                             int tid) {
    const __nv_bfloat16* Kg = g_t + kt * 64 * 128;
    uint32_t kB = sbase + (buf ? SM_K1 : SM_K0);
#pragma unroll
    for (int j = 0; j < 4; j++) {
        int i = tid + j * 256;
        int r = i >> 4, c = i & 15;
        cp_async16(kB + r * RSB + c * 16, Kg + r * 128 + c * 8);
    }
}
__device__ __forceinline__ void load_V_async(uint32_t sbase, int buf, int kt,
                                             int tid) {
    const __nv_bfloat16* Vg = g_zb + kt * 64 * 128;
    uint32_t vB = sbase + (buf ? SM_V1 : SM_V0);
#pragma unroll
    for (int j = 0; j < 4; j++) {
        int i = tid + j * 256;
        int r = i >> 4, c = i & 15;
        cp_async16(vB + r * RSB + c * 16, Vg + r * 128 + c * 8);
    }
}

__device__ __forceinline__ void pv_block(uint32_t vB, const uint32_t pf[2][4],
                                         float o[16][4], int vrow, int vcol) {
#pragma unroll
    for (int dn16 = 0; dn16 < 8; dn16++) {
#pragma unroll
        for (int kc2 = 0; kc2 < 2; kc2++) {
            uint32_t r0, r1, r2, r3;
            uint32_t a = vB + (vrow + kc2 * 16) * RSB + (dn16 * 16 + vcol) * 2;
            ldm_x4_t(r0, r1, r2, r3, a);
            mma16816(o[2 * dn16], pf[kc2], r0, r1);
            mma16816(o[2 * dn16 + 1], pf[kc2], r2, r3);
        }
    }
}

__global__ __launch_bounds__(256, 1) void flash_kernel(
    const float* __restrict__ Z, float* __restrict__ out)
{
    __nv_bfloat16* sm = (__nv_bfloat16*)dynsmem;
    const uint32_t sbase = smem_u32(sm);

    const int tid = threadIdx.x;
    const int lane = tid & 31;
    const int warp = tid >> 5;
    const int wg = warp >> 2;    // key-split group (0/1)
    const int w4 = warp & 3;     // row-block warp id
    const int g = lane >> 2;
    const int rb = blockIdx.x * 64;

    // ---- stage Q tile into K0 region, extract A-fragments via ldmatrix ----
#pragma unroll
    for (int j = 0; j < 4; j++) {
        int i = tid + j * 256;
        int r = i >> 4, c = i & 15;
        *(uint4*)&sm[r * RSH + c * 8] = *(const uint4*)&g_t[(rb + r) * 128 + c * 8];
    }
    __syncthreads();
    uint32_t qf[8][4];
    {
        int qrow = w4 * 16 + (lane & 7) + ((lane >> 3) & 1) * 8;
        int qcol = (lane >> 4) * 8;
#pragma unroll
        for (int kc = 0; kc < 8; kc++) {
            uint32_t a = sbase + qrow * RSB + (kc * 16 + qcol) * 2;
            ldm_x4(qf[kc][0], qf[kc][1], qf[kc][2], qf[kc][3], a);
        }
    }
    __syncthreads();

    const int r0q = rb + w4 * 16 + g;
    const float M0 = g_diag[r0q];
    const float M1 = g_diag[r0q + 8];

    // ---- prologue: K0 (group A); K1+V0 (group B) ----
    load_K_async(sbase, 0, 0, tid);
    cp_commit();
    load_K_async(sbase, 1, 1, tid);
    load_V_async(sbase, 0, 0, tid);
    cp_commit();

    float o[16][4];
#pragma unroll
    for (int dn = 0; dn < 16; dn++) {
        o[dn][0] = 0.f; o[dn][1] = 0.f; o[dn][2] = 0.f; o[dn][3] = 0.f;
    }
    float l0 = 0.f, l1 = 0.f;
    uint32_t pf[2][4];

    const int krow = wg * 32 + (lane & 7) + ((lane >= 16) ? 8 : 0);
    const int kcol = ((lane >> 3) & 1) * 8;
    const int vrow = wg * 32 + (lane & 15);
    const int vcol = (lane >> 4) * 8;

    for (int kt = 0; kt < NN / 64; kt++) {
        cp_wait<1>();        // K(kt) and V(kt-1) complete
        __syncthreads();

        const uint32_t kB = sbase + ((kt & 1) ? SM_K1 : SM_K0);

        // ---- S(kt) = Q K^T over this group's 32 keys ----
        float sc[4][4];
#pragma unroll
        for (int nc = 0; nc < 4; nc++) {
            sc[nc][0] = 0.f; sc[nc][1] = 0.f; sc[nc][2] = 0.f; sc[nc][3] = 0.f;
        }
#pragma unroll
        for (int nc16 = 0; nc16 < 2; nc16++) {
#pragma unroll
            for (int kc = 0; kc < 8; kc++) {
                uint32_t r0, r1, r2, r3;
                uint32_t a = kB + (krow + nc16 * 16) * RSB + (kc * 16 + kcol) * 2;
                ldm_x4(r0, r1, r2, r3, a);
                mma16816(sc[2 * nc16], qf[kc], r0, r1);
                mma16816(sc[2 * nc16 + 1], qf[kc], r2, r3);
            }
        }

        // ---- PV(kt-1): independent of S(kt) results — covers the S wait ----
        if (kt > 0) {
            const uint32_t vB = sbase + (((kt - 1) & 1) ? SM_V1 : SM_V0);
            pv_block(vB, pf, o, vrow, vcol);
        }
        __syncthreads();   // all warps done reading K(kt) buf and V(kt-1) buf

        // ---- prefetch K(kt+2) into current K buf, V(kt+1) into other V buf --
        if (kt + 2 < NN / 64) load_K_async(sbase, kt & 1, kt + 2, tid);
        if (kt + 1 < NN / 64) load_V_async(sbase, (kt + 1) & 1, kt + 1, tid);
        cp_commit();

        // ---- softmax(kt): p = exp2(s - M) -> pf for next iteration's PV ----
#pragma unroll
        for (int nc = 0; nc < 4; nc++) {
            float e0 = ex2(sc[nc][0] - M0);
            float e1 = ex2(sc[nc][1] - M0);
            float e2 = ex2(sc[nc][2] - M1);
            float e3 = ex2(sc[nc][3] - M1);
            l0 += e0 + e1; l1 += e2 + e3;
            if (nc & 1) { pf[nc >> 1][2] = packbf(e0, e1); pf[nc >> 1][3] = packbf(e2, e3); }
            else        { pf[nc >> 1][0] = packbf(e0, e1); pf[nc >> 1][1] = packbf(e2, e3); }
        }
    }

    // ---- epilogue PV for the final tile ----
    cp_wait<0>();
    __syncthreads();
    {
        const uint32_t vB = sbase + (((NN / 64 - 1) & 1) ? SM_V1 : SM_V0);
        pv_block(vB, pf, o, vrow, vcol);
    }

    // one-time l reduction across the quad (lanes sharing a row)
    l0 += __shfl_xor_sync(0xffffffffu, l0, 1);
    l0 += __shfl_xor_sync(0xffffffffu, l0, 2);
    l1 += __shfl_xor_sync(0xffffffffu, l1, 1);
    l1 += __shfl_xor_sync(0xffffffffu, l1, 2);

    // ---- merge the two key-split partials (plain adds — same shift M) ----
    float* obuf = (float*)dynsmem;                      // [128][68] over K0/K1
    float* statb = (float*)(dynsmem + 128 * 68 * 4);    // [128][2] (start of V0)
    const int tt = tid & 127;
    if (wg == 1) {
#pragma unroll
        for (int dn = 0; dn < 16; dn++) {
            *(float4*)&obuf[tt * 68 + dn * 4] =
                make_float4(o[dn][0], o[dn][1], o[dn][2], o[dn][3]);
        }
        statb[tt * 2] = l0;
        statb[tt * 2 + 1] = l1;
    }
    __syncthreads();
    if (wg == 0) {
        l0 += statb[tt * 2];
        l1 += statb[tt * 2 + 1];
        const float i0 = 1.f / l0, i1 = 1.f / l1;
        const int t4 = lane & 3;
        const int r0r = rb + w4 * 16 + g, r1r = r0r + 8;
#pragma unroll
        for (int dn = 0; dn < 16; dn++) {
            float4 po = *(const float4*)&obuf[tt * 68 + dn * 4];
            float v0 = o[dn][0] + po.x;
            float v1 = o[dn][1] + po.y;
            float v2 = o[dn][2] + po.z;
            float v3 = o[dn][3] + po.w;
            int c = dn * 8 + 2 * t4;
            float z00 = Z[r0r * 128 + c], z01 = Z[r0r * 128 + c + 1];
            float z10 = Z[r1r * 128 + c], z11 = Z[r1r * 128 + c + 1];
            out[r0r * 128 + c]     = z00 + TAU * (v0 * i0 - z00);
            out[r0r * 128 + c + 1] = z01 + TAU * (v1 * i0 - z01);
            out[r1r * 128 + c]     = z10 + TAU * (v2 * i1 - z10);
            out[r1r * 128 + c + 1] = z11 + TAU * (v3 * i1 - z11);
        }
    }
}

extern "C" void kernel_launch(void* const* d_in, const int* in_sizes, int n_in,
                              void* d_out, int out_size)
{
    (void)in_sizes; (void)n_in; (void)out_size;
    const float* Z  = (const float*)d_in[0];
    const float* W1 = (const float*)d_in[1];
    const float* b1 = (const float*)d_in[2];
    const float* W2 = (const float*)d_in[3];
    const float* b2 = (const float*)d_in[4];
    float* out = (float*)d_out;

    cudaFuncSetAttribute(mlp_kernel,
                         cudaFuncAttributeMaxDynamicSharedMemorySize, SMEM_TOTAL);
    cudaFuncSetAttribute(flash_kernel,
                         cudaFuncAttributeMaxDynamicSharedMemorySize, SMEM_TOTAL);

    mlp_kernel<<<128, 256, SMEM_TOTAL>>>(Z, W1, b1, W2, b2);
    flash_kernel<<<128, 256, SMEM_TOTAL>>>(Z, out);
}